// round 1
// baseline (speedup 1.0000x reference)
#include <cuda_runtime.h>

#define BB  4096
#define TT  500
#define FF  40
#define HH  128
#define OO  5
#define BETA 0.9f
#define THR  1.0f

typedef unsigned long long u64;

__device__ __forceinline__ u64 pack2(float lo, float hi) {
    u64 r; asm("mov.b64 %0, {%1, %2};" : "=l"(r) : "f"(lo), "f"(hi)); return r;
}
__device__ __forceinline__ void unpack2(u64 v, float& lo, float& hi) {
    asm("mov.b64 {%0, %1}, %2;" : "=f"(lo), "=f"(hi) : "l"(v));
}
__device__ __forceinline__ u64 fma2(u64 a, u64 b, u64 c) {
    u64 d; asm("fma.rn.f32x2 %0, %1, %2, %3;" : "=l"(d) : "l"(a), "l"(b), "l"(c)); return d;
}

// 1 warp = 1 batch element. thread lane handles neurons {l, l+32, l+64, l+96}
// as two f32x2 pairs. W1 (4 rows x 40) held in ~160 registers per thread.
__global__ __launch_bounds__(128, 2)
void snn_kernel(const float* __restrict__ x,  const float* __restrict__ W1,
                const float* __restrict__ b1, const float* __restrict__ W2,
                const float* __restrict__ b2, float* __restrict__ out)
{
    __shared__ float sbuf[4][2][FF];   // [warp][stage][feature]
    const int lane = threadIdx.x & 31;
    const int warp = threadIdx.x >> 5;
    const int b    = blockIdx.x * 4 + warp;

    const int n0 = lane, n1 = lane + 32, n2 = lane + 64, n3 = lane + 96;

    // ---- preload W1 as packed pairs (registers) ----
    u64 wA[FF], wB[FF];
#pragma unroll
    for (int k = 0; k < FF; k++) {
        wA[k] = pack2(W1[n0 * FF + k], W1[n1 * FF + k]);
        wB[k] = pack2(W1[n2 * FF + k], W1[n3 * FF + k]);
    }
    const u64 biasA = pack2(b1[n0], b1[n1]);
    const u64 biasB = pack2(b1[n2], b1[n3]);

    // ---- preload W2 columns for this thread's 4 neurons ----
    float w2r[4][OO];
#pragma unroll
    for (int o = 0; o < OO; o++) {
        w2r[0][o] = W2[o * HH + n0];
        w2r[1][o] = W2[o * HH + n1];
        w2r[2][o] = W2[o * HH + n2];
        w2r[3][o] = W2[o * HH + n3];
    }
    const float b2l = b2[lane < OO ? lane : OO - 1];

    float m1[4] = {0.f, 0.f, 0.f, 0.f};
    float m2 = 0.f;

    const float* xb = x + (size_t)b * TT * FF;
    float*       ob = out + (size_t)b * OO;

    // ---- prologue: stage x[t=0] into shared ----
    if (lane < 10) {
        float4 x0 = __ldcs((const float4*)xb + lane);
        *((float4*)sbuf[warp][0] + lane) = x0;
    }
    __syncwarp();

    int stage = 0;
    for (int t = 0; t < TT; t++) {
        // prefetch x[t+1] (clamped) into registers; STS at loop end
        const int tn = (t + 1 < TT) ? t + 1 : TT - 1;
        float4 xn;
        if (lane < 10)
            xn = __ldcs((const float4*)(xb + (size_t)tn * FF) + lane);

        // ---- layer 1: cur1 = x[t] @ W1^T + b1  (packed f32x2 FMAs) ----
        u64 accA = biasA, accB = biasB;
        const float* xs = sbuf[warp][stage];
#pragma unroll
        for (int j = 0; j < FF / 4; j++) {
            const float4 xq = *((const float4*)xs + j);
            u64 p;
            p = pack2(xq.x, xq.x); accA = fma2(p, wA[4*j+0], accA); accB = fma2(p, wB[4*j+0], accB);
            p = pack2(xq.y, xq.y); accA = fma2(p, wA[4*j+1], accA); accB = fma2(p, wB[4*j+1], accB);
            p = pack2(xq.z, xq.z); accA = fma2(p, wA[4*j+2], accA); accB = fma2(p, wB[4*j+2], accB);
            p = pack2(xq.w, xq.w); accA = fma2(p, wA[4*j+3], accA); accB = fma2(p, wB[4*j+3], accB);
        }
        float cur[4];
        unpack2(accA, cur[0], cur[1]);
        unpack2(accB, cur[2], cur[3]);

        // ---- LIF layer 1: reset from PREVIOUS m, then update, then spike ----
        bool spk[4];
#pragma unroll
        for (int i = 0; i < 4; i++) {
            const bool rst = m1[i] > THR;
            float m = fmaf(BETA, m1[i], cur[i]);
            if (rst) m -= THR;
            m1[i] = m;
            spk[i] = m > THR;
        }

        // ---- layer 2 partials: spikes are 0/1 -> predicated adds ----
        float s[OO];
#pragma unroll
        for (int o = 0; o < OO; o++) {
            float v = 0.f;
            if (spk[0]) v += w2r[0][o];
            if (spk[1]) v += w2r[1][o];
            if (spk[2]) v += w2r[2][o];
            if (spk[3]) v += w2r[3][o];
            s[o] = v;
        }
        // butterfly reduce 5 sums across the warp
#pragma unroll
        for (int off = 16; off; off >>= 1) {
#pragma unroll
            for (int o = 0; o < OO; o++)
                s[o] += __shfl_xor_sync(0xffffffffu, s[o], off);
        }

        // ---- LIF layer 2: state lives on lanes 0..4 ----
        float cur2 = (lane == 0) ? s[0]
                   : (lane == 1) ? s[1]
                   : (lane == 2) ? s[2]
                   : (lane == 3) ? s[3] : s[4];
        cur2 += b2l;
        const bool rst2 = m2 > THR;
        float mm = fmaf(BETA, m2, cur2);
        if (rst2) mm -= THR;
        m2 = mm;
        const float spk2 = (mm > THR) ? 1.0f : 0.0f;
        if (lane < OO)
            __stcs(ob + (size_t)t * BB * OO + lane, spk2);

        // ---- stage x[t+1] ----
        if (lane < 10)
            *((float4*)sbuf[warp][stage ^ 1] + lane) = xn;
        __syncwarp();
        stage ^= 1;
    }
}

extern "C" void kernel_launch(void* const* d_in, const int* in_sizes, int n_in,
                              void* d_out, int out_size) {
    const float* x  = (const float*)d_in[0];
    const float* W1 = (const float*)d_in[1];
    const float* b1 = (const float*)d_in[2];
    const float* W2 = (const float*)d_in[3];
    const float* b2 = (const float*)d_in[4];
    float* out = (float*)d_out;
    snn_kernel<<<BB / 4, 128>>>(x, W1, b1, W2, b2, out);
}

// round 3
// speedup vs baseline: 1.1351x; 1.1351x over previous
#include <cuda_runtime.h>

#define BB  4096
#define TT  500
#define FF  40
#define HH  128
#define OO  5
#define BETA 0.9f
#define THR  1.0f

typedef unsigned long long u64;

__device__ __forceinline__ u64 pack2(float lo, float hi) {
    u64 r; asm("mov.b64 %0, {%1, %2};" : "=l"(r) : "f"(lo), "f"(hi)); return r;
}
__device__ __forceinline__ void unpack2(u64 v, float& lo, float& hi) {
    asm("mov.b64 {%0, %1}, %2;" : "=f"(lo), "=f"(hi) : "l"(v));
}
__device__ __forceinline__ u64 fma2(u64 a, u64 b, u64 c) {
    u64 d; asm("fma.rn.f32x2 %0, %1, %2, %3;" : "=l"(d) : "l"(a), "l"(b), "l"(c)); return d;
}

// Layer-1 for both batches: 4 independent packed-FMA chains.
// Per-neuron order (bias first, k ascending) identical to the bitwise-exact R1.
#define LAYER1(STG, C0, C1) do {                                               \
    const float* xs0 = sbuf[warp][STG][0];                                     \
    const float* xs1 = sbuf[warp][STG][1];                                     \
    u64 aA = biasA, aB = biasB, bA = biasA, bB = biasB;                        \
    _Pragma("unroll")                                                          \
    for (int j = 0; j < FF / 4; j++) {                                         \
        const float4 q0 = *((const float4*)xs0 + j);                           \
        const float4 q1 = *((const float4*)xs1 + j);                           \
        u64 p;                                                                 \
        p = pack2(q0.x, q0.x); aA = fma2(p, wA[4*j+0], aA); aB = fma2(p, wB[4*j+0], aB); \
        p = pack2(q1.x, q1.x); bA = fma2(p, wA[4*j+0], bA); bB = fma2(p, wB[4*j+0], bB); \
        p = pack2(q0.y, q0.y); aA = fma2(p, wA[4*j+1], aA); aB = fma2(p, wB[4*j+1], aB); \
        p = pack2(q1.y, q1.y); bA = fma2(p, wA[4*j+1], bA); bB = fma2(p, wB[4*j+1], bB); \
        p = pack2(q0.z, q0.z); aA = fma2(p, wA[4*j+2], aA); aB = fma2(p, wB[4*j+2], aB); \
        p = pack2(q1.z, q1.z); bA = fma2(p, wA[4*j+2], bA); bB = fma2(p, wB[4*j+2], bB); \
        p = pack2(q0.w, q0.w); aA = fma2(p, wA[4*j+3], aA); aB = fma2(p, wB[4*j+3], aB); \
        p = pack2(q1.w, q1.w); bA = fma2(p, wA[4*j+3], bA); bB = fma2(p, wB[4*j+3], bB); \
    }                                                                          \
    unpack2(aA, C0[0], C0[1]); unpack2(aB, C0[2], C0[3]);                      \
    unpack2(bA, C1[0], C1[1]); unpack2(bB, C1[2], C1[3]);                      \
} while (0)

// LIF layer-1 update + layer-2 partial sums (spikes are 0/1 -> predicated adds)
#define LIF_PART(C0, C1) do {                                                  \
    bool s0[4], s1[4];                                                         \
    _Pragma("unroll")                                                          \
    for (int i = 0; i < 4; i++) {                                              \
        const bool r0 = m1a[i] > THR;                                          \
        float ma = fmaf(BETA, m1a[i], C0[i]); if (r0) ma -= THR;               \
        m1a[i] = ma; s0[i] = ma > THR;                                         \
        const bool r1 = m1b[i] > THR;                                          \
        float mb = fmaf(BETA, m1b[i], C1[i]); if (r1) mb -= THR;               \
        m1b[i] = mb; s1[i] = mb > THR;                                         \
    }                                                                          \
    _Pragma("unroll")                                                          \
    for (int o = 0; o < OO; o++) {                                             \
        float v = 0.f;                                                         \
        if (s0[0]) v += w2r[0][o]; if (s0[1]) v += w2r[1][o];                  \
        if (s0[2]) v += w2r[2][o]; if (s0[3]) v += w2r[3][o];                  \
        pa[o] = v;                                                             \
        float w = 0.f;                                                         \
        if (s1[0]) w += w2r[0][o]; if (s1[1]) w += w2r[1][o];                  \
        if (s1[2]) w += w2r[2][o]; if (s1[3]) w += w2r[3][o];                  \
        pb[o] = w;                                                             \
    }                                                                          \
} while (0)

// Deferred: butterfly-reduce previous step's partials, LIF layer-2, store.
#define REDUCE_STORE(TPREV) do {                                               \
    _Pragma("unroll")                                                          \
    for (int off = 16; off; off >>= 1) {                                       \
        _Pragma("unroll")                                                      \
        for (int o = 0; o < OO; o++) {                                         \
            pa[o] += __shfl_xor_sync(0xffffffffu, pa[o], off);                 \
            pb[o] += __shfl_xor_sync(0xffffffffu, pb[o], off);                 \
        }                                                                      \
    }                                                                          \
    const float ra = (oid == 0) ? pa[0] : (oid == 1) ? pa[1]                   \
                   : (oid == 2) ? pa[2] : (oid == 3) ? pa[3] : pa[4];          \
    const float rb = (oid == 0) ? pb[0] : (oid == 1) ? pb[1]                   \
                   : (oid == 2) ? pb[2] : (oid == 3) ? pb[3] : pb[4];          \
    const float cur2 = ((lane < 8) ? ra : rb) + b2l;                           \
    const bool rst2 = m2v > THR;                                               \
    float mm = fmaf(BETA, m2v, cur2); if (rst2) mm -= THR;                     \
    m2v = mm;                                                                  \
    if (out_lane)                                                              \
        __stcs(op + (size_t)(TPREV) * BB * OO + ((lane >= 8) ? OO : 0) + oid,  \
               (mm > THR) ? 1.0f : 0.0f);                                      \
} while (0)

#define PREFETCH(TN) do {                                                      \
    if (lane < 10)                                                             \
        xn = __ldcs((const float4*)(xp0 + (size_t)(TN) * FF) + lane);          \
    else if (lane >= 16 && lane < 26)                                          \
        xn = __ldcs((const float4*)(xp1 + (size_t)(TN) * FF) + (lane - 16));   \
} while (0)

#define STAGE_STS(STG) do {                                                    \
    if (lane < 10)                                                             \
        *((float4*)sbuf[warp][STG][0] + lane) = xn;                            \
    else if (lane >= 16 && lane < 26)                                          \
        *((float4*)sbuf[warp][STG][1] + (lane - 16)) = xn;                     \
} while (0)

// 1 warp = 2 batch elements; W1 registers shared across both.
__global__ __launch_bounds__(128, 2)
void snn_kernel(const float* __restrict__ x,  const float* __restrict__ W1,
                const float* __restrict__ b1, const float* __restrict__ W2,
                const float* __restrict__ b2, float* __restrict__ out)
{
    __shared__ float sbuf[4][2][2][FF];   // [warp][stage][batch-in-warp][feature]
    const int lane = threadIdx.x & 31;
    const int warp = threadIdx.x >> 5;
    const int b0   = (blockIdx.x * 4 + warp) * 2;

    const int n0 = lane, n1 = lane + 32, n2 = lane + 64, n3 = lane + 96;

    u64 wA[FF], wB[FF];
#pragma unroll
    for (int k = 0; k < FF; k++) {
        wA[k] = pack2(W1[n0 * FF + k], W1[n1 * FF + k]);
        wB[k] = pack2(W1[n2 * FF + k], W1[n3 * FF + k]);
    }
    const u64 biasA = pack2(b1[n0], b1[n1]);
    const u64 biasB = pack2(b1[n2], b1[n3]);

    float w2r[4][OO];
#pragma unroll
    for (int o = 0; o < OO; o++) {
        w2r[0][o] = W2[o * HH + n0];
        w2r[1][o] = W2[o * HH + n1];
        w2r[2][o] = W2[o * HH + n2];
        w2r[3][o] = W2[o * HH + n3];
    }
    const int   oid      = lane & 7;
    const float b2l      = b2[oid < OO ? oid : 0];
    const bool  out_lane = (lane < OO) || (lane >= 8 && lane < 8 + OO);

    float m1a[4] = {0.f, 0.f, 0.f, 0.f};
    float m1b[4] = {0.f, 0.f, 0.f, 0.f};
    float m2v = 0.f;
    float pa[OO], pb[OO];

    const float* xp0 = x + (size_t)b0 * TT * FF;
    const float* xp1 = xp0 + (size_t)TT * FF;
    float*       op  = out + (size_t)b0 * OO;

    // stage x[0]
    if (lane < 10)
        *((float4*)sbuf[warp][0][0] + lane) = __ldcs((const float4*)xp0 + lane);
    else if (lane >= 16 && lane < 26)
        *((float4*)sbuf[warp][0][1] + (lane - 16)) = __ldcs((const float4*)xp1 + (lane - 16));
    __syncwarp();

    float4 xn;
    float c0[4], c1[4];

    // ---- peeled t = 0 (no deferred reduce yet) ----
    PREFETCH(1);
    LAYER1(0, c0, c1);
    LIF_PART(c0, c1);
    STAGE_STS(1);
    __syncwarp();

    int stage = 1;
#pragma unroll 1
    for (int t = 1; t < TT; t++) {
        const int tn = (t + 1 < TT) ? t + 1 : TT - 1;
        PREFETCH(tn);
        LAYER1(stage, c0, c1);      // FMA stream for step t
        REDUCE_STORE(t - 1);        // SHFL stream for step t-1 (independent, hides latency)
        LIF_PART(c0, c1);           // consumes FMA results, refills pa/pb
        STAGE_STS(stage ^ 1);
        __syncwarp();
        stage ^= 1;
    }

    // ---- epilogue: reduce + store final step ----
    REDUCE_STORE(TT - 1);
}

extern "C" void kernel_launch(void* const* d_in, const int* in_sizes, int n_in,
                              void* d_out, int out_size) {
    const float* x  = (const float*)d_in[0];
    const float* W1 = (const float*)d_in[1];
    const float* b1 = (const float*)d_in[2];
    const float* W2 = (const float*)d_in[3];
    const float* b2 = (const float*)d_in[4];
    float* out = (float*)d_out;
    snn_kernel<<<BB / 8, 128>>>(x, W1, b1, W2, b2, out);
}

// round 4
// speedup vs baseline: 1.4415x; 1.2699x over previous
#include <cuda_runtime.h>

#define BB  4096
#define TT  500
#define FF  40
#define HH  128
#define OO  5
#define NB  4          // batches per warp
#define BETA 0.9f
#define THR  1.0f

typedef unsigned long long u64;

__device__ __forceinline__ u64 pack2(float lo, float hi) {
    u64 r; asm("mov.b64 %0, {%1, %2};" : "=l"(r) : "f"(lo), "f"(hi)); return r;
}
__device__ __forceinline__ void unpack2(u64 v, float& lo, float& hi) {
    asm("mov.b64 {%0, %1}, %2;" : "=f"(lo), "=f"(hi) : "l"(v));
}
__device__ __forceinline__ u64 fma2(u64 a, u64 b, u64 c) {
    u64 d; asm("fma.rn.f32x2 %0, %1, %2, %3;" : "=l"(d) : "l"(a), "l"(b), "l"(c)); return d;
}

// 1 warp = 4 batch elements, W1 shared in registers across all 4 (8 FMA chains).
// lane owns neurons {l, l+32, l+64, l+96}. Layer-1 per-neuron accumulation order
// (bias first, k ascending) identical to the bitwise-exact R1/R3 kernels.
__global__ __launch_bounds__(128, 2)
void snn_kernel(const float* __restrict__ x,  const float* __restrict__ W1,
                const float* __restrict__ b1, const float* __restrict__ W2,
                const float* __restrict__ b2, float* __restrict__ out)
{
    __shared__ float sbuf[4][2][NB][FF];   // [warp][stage][batch][feature]
    const int lane = threadIdx.x & 31;
    const int warp = threadIdx.x >> 5;
    const int b0   = (blockIdx.x * 4 + warp) * NB;

    const int n0 = lane, n1 = lane + 32, n2 = lane + 64, n3 = lane + 96;

    // ---- W1 packed pairs in registers (shared by all 4 batches) ----
    u64 wA[FF], wB[FF];
#pragma unroll
    for (int k = 0; k < FF; k++) {
        wA[k] = pack2(W1[n0 * FF + k], W1[n1 * FF + k]);
        wB[k] = pack2(W1[n2 * FF + k], W1[n3 * FF + k]);
    }
    const u64 biasA = pack2(b1[n0], b1[n1]);
    const u64 biasB = pack2(b1[n2], b1[n3]);

    float w2r[4][OO];
#pragma unroll
    for (int o = 0; o < OO; o++) {
        w2r[0][o] = W2[o * HH + n0];
        w2r[1][o] = W2[o * HH + n1];
        w2r[2][o] = W2[o * HH + n2];
        w2r[3][o] = W2[o * HH + n3];
    }
    const int   oid  = lane & 7;     // output id within batch group
    const int   qsel = lane >> 3;    // which batch this lane's output belongs to
    const float b2l  = b2[oid < OO ? oid : 0];
    const bool  do_store = (oid < OO);

    // ---- staging map: 40 float4-chunks (4 batches x 10) over 32 lanes ----
    const int  q1i = (lane >= 30) ? 3 : (lane >= 20) ? 2 : (lane >= 10) ? 1 : 0;
    const int  r1i = lane - q1i * 10;
    const bool do2 = (lane < 8);
    const int  r2i = lane + 2;       // second chunk: batch 3, quads 2..9

    const float* xg1 = x + (size_t)(b0 + q1i) * TT * FF + r1i * 4;
    const float* xg2 = x + (size_t)(b0 + 3)   * TT * FF + r2i * 4;
    float*       ob  = out + (size_t)b0 * OO;

    float m1v[NB][4];
#pragma unroll
    for (int b = 0; b < NB; b++)
#pragma unroll
        for (int i = 0; i < 4; i++) m1v[b][i] = 0.f;
    float m2v = 0.f;

    // ---- de-convoy skew: co-resident CTA pair (bid, bid+148) differ in bit 2 ----
    {
        float dummy = 1.0f;
        const int skew = ((blockIdx.x >> 2) & 1) * 96;
#pragma unroll 1
        for (int i = 0; i < skew; i++)
            asm volatile("add.f32 %0, %0, %0;" : "+f"(dummy));
        if (dummy == 1.5f) __stcs(ob, 0.0f);   // never true; keeps chain live
    }

    // ---- prologue: stage x[t=0] ----
    *((float4*)&sbuf[warp][0][q1i][r1i * 4]) = __ldcs((const float4*)xg1);
    if (do2)
        *((float4*)&sbuf[warp][0][3][r2i * 4]) = __ldcs((const float4*)xg2);
    __syncwarp();

    int stage = 0;
#pragma unroll 1
    for (int t = 0; t < TT; t++) {
        // prefetch x[t+1] (clamped)
        const int tn = (t + 1 < TT) ? t + 1 : TT - 1;
        const float4 xa = __ldcs((const float4*)(xg1 + (size_t)tn * FF));
        float4 xb;
        if (do2) xb = __ldcs((const float4*)(xg2 + (size_t)tn * FF));

        // ---- layer 1: 4 batches = 8 independent packed-FMA chains ----
        u64 acc[NB][2];
#pragma unroll
        for (int b = 0; b < NB; b++) { acc[b][0] = biasA; acc[b][1] = biasB; }
#pragma unroll
        for (int j = 0; j < FF / 4; j++) {
            float4 xq[NB];
#pragma unroll
            for (int b = 0; b < NB; b++)
                xq[b] = *((const float4*)&sbuf[warp][stage][b][j * 4]);
#pragma unroll
            for (int b = 0; b < NB; b++) {
                u64 p;
                p = pack2(xq[b].x, xq[b].x);
                acc[b][0] = fma2(p, wA[4*j+0], acc[b][0]);
                acc[b][1] = fma2(p, wB[4*j+0], acc[b][1]);
                p = pack2(xq[b].y, xq[b].y);
                acc[b][0] = fma2(p, wA[4*j+1], acc[b][0]);
                acc[b][1] = fma2(p, wB[4*j+1], acc[b][1]);
                p = pack2(xq[b].z, xq[b].z);
                acc[b][0] = fma2(p, wA[4*j+2], acc[b][0]);
                acc[b][1] = fma2(p, wB[4*j+2], acc[b][1]);
                p = pack2(xq[b].w, xq[b].w);
                acc[b][0] = fma2(p, wA[4*j+3], acc[b][0]);
                acc[b][1] = fma2(p, wB[4*j+3], acc[b][1]);
            }
        }

        // ---- LIF layer 1 + layer-2 partials ----
        float P[NB][OO];
#pragma unroll
        for (int b = 0; b < NB; b++) {
            float cur[4];
            unpack2(acc[b][0], cur[0], cur[1]);
            unpack2(acc[b][1], cur[2], cur[3]);
            bool s[4];
#pragma unroll
            for (int i = 0; i < 4; i++) {
                const bool rst = m1v[b][i] > THR;
                float m = fmaf(BETA, m1v[b][i], cur[i]);
                if (rst) m -= THR;
                m1v[b][i] = m;
                s[i] = m > THR;
            }
#pragma unroll
            for (int o = 0; o < OO; o++) {
                float v = 0.f;
                if (s[0]) v += w2r[0][o];
                if (s[1]) v += w2r[1][o];
                if (s[2]) v += w2r[2][o];
                if (s[3]) v += w2r[3][o];
                P[b][o] = v;
            }
        }

        // ---- butterfly reduce (same structure as the rel_err=0 kernels) ----
#pragma unroll
        for (int off = 16; off; off >>= 1)
#pragma unroll
            for (int b = 0; b < NB; b++)
#pragma unroll
                for (int o = 0; o < OO; o++)
                    P[b][o] += __shfl_xor_sync(0xffffffffu, P[b][o], off);

        // ---- each lane picks its (batch, output) sum ----
        float pv[NB];
#pragma unroll
        for (int b = 0; b < NB; b++)
            pv[b] = (oid == 0) ? P[b][0] : (oid == 1) ? P[b][1]
                  : (oid == 2) ? P[b][2] : (oid == 3) ? P[b][3] : P[b][4];
        const float rsum = (qsel == 0) ? pv[0] : (qsel == 1) ? pv[1]
                         : (qsel == 2) ? pv[2] : pv[3];

        // ---- LIF layer 2 + store (20 lanes active) ----
        const float cur2 = rsum + b2l;
        const bool rst2 = m2v > THR;
        float mm = fmaf(BETA, m2v, cur2);
        if (rst2) mm -= THR;
        m2v = mm;
        if (do_store)
            __stcs(ob + (size_t)t * BB * OO + qsel * OO + oid,
                   (mm > THR) ? 1.0f : 0.0f);

        // ---- stage x[t+1] ----
        *((float4*)&sbuf[warp][stage ^ 1][q1i][r1i * 4]) = xa;
        if (do2)
            *((float4*)&sbuf[warp][stage ^ 1][3][r2i * 4]) = xb;
        __syncwarp();
        stage ^= 1;
    }
}

extern "C" void kernel_launch(void* const* d_in, const int* in_sizes, int n_in,
                              void* d_out, int out_size) {
    const float* x  = (const float*)d_in[0];
    const float* W1 = (const float*)d_in[1];
    const float* b1 = (const float*)d_in[2];
    const float* W2 = (const float*)d_in[3];
    const float* b2 = (const float*)d_in[4];
    float* out = (float*)d_out;
    snn_kernel<<<BB / (4 * NB), 128>>>(x, W1, b1, W2, b2, out);
}

// round 5
// speedup vs baseline: 1.7918x; 1.2430x over previous
#include <cuda_runtime.h>

#define BB  4096
#define TT  500
#define FF  40
#define HH  128
#define OO  5
#define NB  4          // batches per warp
#define BETA 0.9f
#define THR  1.0f

#define LUT_FLOATS (OO * 16 * 256)           // 20480
#define STG_FLOATS (4 * 2 * NB * FF)         // 1280
#define DYN_SMEM   ((LUT_FLOATS + STG_FLOATS) * 4)

typedef unsigned long long u64;
typedef unsigned int u32;

__device__ float4 g_lut4[LUT_FLOATS / 4];

__device__ __forceinline__ u64 pack2(float lo, float hi) {
    u64 r; asm("mov.b64 %0, {%1, %2};" : "=l"(r) : "f"(lo), "f"(hi)); return r;
}
__device__ __forceinline__ void unpack2(u64 v, float& lo, float& hi) {
    asm("mov.b64 {%0, %1}, %2;" : "=f"(lo), "=f"(hi) : "l"(v));
}
__device__ __forceinline__ u64 fma2(u64 a, u64 b, u64 c) {
    u64 d; asm("fma.rn.f32x2 %0, %1, %2, %3;" : "=l"(d) : "l"(a), "l"(b), "l"(c)); return d;
}

// LUT[o][seg][v] = sum_{j ascending, bit j set in v} W2[o][seg*8 + j]
__global__ void build_lut_kernel(const float* __restrict__ W2) {
    const int idx = blockIdx.x * blockDim.x + threadIdx.x;
    if (idx >= LUT_FLOATS) return;
    const int v = idx & 255, seg = (idx >> 8) & 15, o = idx >> 12;
    float s = 0.f;
#pragma unroll
    for (int j = 0; j < 8; j++)
        if (v & (1 << j)) s += W2[o * HH + seg * 8 + j];
    ((float*)g_lut4)[idx] = s;
}

// 1 warp = 4 batch elements; W1 shared in registers (8 packed-FMA chains).
// Layer-1 per-neuron accumulation order (bias first, k ascending) identical
// to the bitwise-exact R1/R3/R4 kernels. Layer 2 via ballot + byte-LUT.
__global__ __launch_bounds__(128, 2)
void snn_kernel(const float* __restrict__ x,  const float* __restrict__ W1,
                const float* __restrict__ b1, const float* __restrict__ b2,
                float* __restrict__ out)
{
    extern __shared__ float smem_dyn[];
    float* lut = smem_dyn;                                   // 20480 floats
    float (*sbuf)[2][NB][FF] = (float (*)[2][NB][FF])(smem_dyn + LUT_FLOATS);

    const int lane = threadIdx.x & 31;
    const int warp = threadIdx.x >> 5;
    const int b0   = (blockIdx.x * 4 + warp) * NB;

    // ---- copy LUT global -> shared (one-time) ----
    for (int i = threadIdx.x; i < LUT_FLOATS / 4; i += 128)
        ((float4*)lut)[i] = g_lut4[i];

    const int n0 = lane, n1 = lane + 32, n2 = lane + 64, n3 = lane + 96;

    // ---- W1 packed pairs in registers (shared by all 4 batches) ----
    u64 wA[FF], wB[FF];
#pragma unroll
    for (int k = 0; k < FF; k++) {
        wA[k] = pack2(W1[n0 * FF + k], W1[n1 * FF + k]);
        wB[k] = pack2(W1[n2 * FF + k], W1[n3 * FF + k]);
    }
    const u64 biasA = pack2(b1[n0], b1[n1]);
    const u64 biasB = pack2(b1[n2], b1[n3]);

    const int   oid  = lane & 7;     // output id within batch group
    const int   qsel = lane >> 3;    // which batch this lane's output belongs to
    const float b2l  = b2[oid < OO ? oid : 0];
    const bool  do_store = (oid < OO);
    const float* lrow = lut + (oid < OO ? oid : 0) * (16 * 256);

    // ---- staging map: 40 float4-chunks (4 batches x 10) over 32 lanes ----
    const int  q1i = (lane >= 30) ? 3 : (lane >= 20) ? 2 : (lane >= 10) ? 1 : 0;
    const int  r1i = lane - q1i * 10;
    const bool do2 = (lane < 8);
    const int  r2i = lane + 2;       // second chunk: batch 3, quads 2..9

    const float* xg1 = x + (size_t)(b0 + q1i) * TT * FF + r1i * 4;
    const float* xg2 = x + (size_t)(b0 + 3)   * TT * FF + r2i * 4;
    float*       ob  = out + (size_t)b0 * OO;

    float m1v[NB][4];
#pragma unroll
    for (int b = 0; b < NB; b++)
#pragma unroll
        for (int i = 0; i < 4; i++) m1v[b][i] = 0.f;
    float m2v = 0.f;

    // ---- de-convoy skew: co-resident CTA pair (bid, bid+148) differ in bit 2 ----
    {
        float dummy = 1.0f;
        const int skew = ((blockIdx.x >> 2) & 1) * 96;
#pragma unroll 1
        for (int i = 0; i < skew; i++)
            asm volatile("add.f32 %0, %0, %0;" : "+f"(dummy));
        if (dummy == 1.5f) __stcs(ob, 0.0f);   // never true; keeps chain live
    }

    // ---- prologue: stage x[t=0] ----
    *((float4*)&sbuf[warp][0][q1i][r1i * 4]) = __ldcs((const float4*)xg1);
    if (do2)
        *((float4*)&sbuf[warp][0][3][r2i * 4]) = __ldcs((const float4*)xg2);
    __syncthreads();   // covers LUT copy + staging

    int stage = 0;
#pragma unroll 1
    for (int t = 0; t < TT; t++) {
        // prefetch x[t+1] (clamped)
        const int tn = (t + 1 < TT) ? t + 1 : TT - 1;
        const float4 xa = __ldcs((const float4*)(xg1 + (size_t)tn * FF));
        float4 xb;
        if (do2) xb = __ldcs((const float4*)(xg2 + (size_t)tn * FF));

        // ---- layer 1: 4 batches = 8 independent packed-FMA chains ----
        u64 acc[NB][2];
#pragma unroll
        for (int b = 0; b < NB; b++) { acc[b][0] = biasA; acc[b][1] = biasB; }
#pragma unroll
        for (int j = 0; j < FF / 4; j++) {
            float4 xq[NB];
#pragma unroll
            for (int b = 0; b < NB; b++)
                xq[b] = *((const float4*)&sbuf[warp][stage][b][j * 4]);
#pragma unroll
            for (int b = 0; b < NB; b++) {
                u64 p;
                p = pack2(xq[b].x, xq[b].x);
                acc[b][0] = fma2(p, wA[4*j+0], acc[b][0]);
                acc[b][1] = fma2(p, wB[4*j+0], acc[b][1]);
                p = pack2(xq[b].y, xq[b].y);
                acc[b][0] = fma2(p, wA[4*j+1], acc[b][0]);
                acc[b][1] = fma2(p, wB[4*j+1], acc[b][1]);
                p = pack2(xq[b].z, xq[b].z);
                acc[b][0] = fma2(p, wA[4*j+2], acc[b][0]);
                acc[b][1] = fma2(p, wB[4*j+2], acc[b][1]);
                p = pack2(xq[b].w, xq[b].w);
                acc[b][0] = fma2(p, wA[4*j+3], acc[b][0]);
                acc[b][1] = fma2(p, wB[4*j+3], acc[b][1]);
            }
        }

        // ---- LIF layer 1 + spike masks via ballot ----
        u32 mk[NB][4];
#pragma unroll
        for (int b = 0; b < NB; b++) {
            float cur[4];
            unpack2(acc[b][0], cur[0], cur[1]);
            unpack2(acc[b][1], cur[2], cur[3]);
#pragma unroll
            for (int i = 0; i < 4; i++) {
                const bool rst = m1v[b][i] > THR;
                float m = fmaf(BETA, m1v[b][i], cur[i]);
                if (rst) m -= THR;
                m1v[b][i] = m;
                mk[b][i] = __ballot_sync(0xffffffffu, m > THR);
            }
        }

        // ---- layer 2: byte-LUT lookups (ascending-h order) ----
        u32 ms[4];
#pragma unroll
        for (int i = 0; i < 4; i++)
            ms[i] = (qsel == 0) ? mk[0][i] : (qsel == 1) ? mk[1][i]
                  : (qsel == 2) ? mk[2][i] : mk[3][i];
        float a2 = 0.f;
#pragma unroll
        for (int i = 0; i < 4; i++) {
#pragma unroll
            for (int j = 0; j < 4; j++) {
                const u32 byte = (ms[i] >> (8 * j)) & 0xFFu;
                const float lv = lrow[(i * 4 + j) * 256 + byte];
                a2 = (i == 0 && j == 0) ? lv : (a2 + lv);
            }
        }

        // ---- LIF layer 2 + store (20 lanes active) ----
        const float cur2 = a2 + b2l;
        const bool rst2 = m2v > THR;
        float mm = fmaf(BETA, m2v, cur2);
        if (rst2) mm -= THR;
        m2v = mm;
        if (do_store)
            __stcs(ob + (size_t)t * BB * OO + qsel * OO + oid,
                   (mm > THR) ? 1.0f : 0.0f);

        // ---- stage x[t+1] ----
        *((float4*)&sbuf[warp][stage ^ 1][q1i][r1i * 4]) = xa;
        if (do2)
            *((float4*)&sbuf[warp][stage ^ 1][3][r2i * 4]) = xb;
        __syncwarp();
        stage ^= 1;
    }
}

extern "C" void kernel_launch(void* const* d_in, const int* in_sizes, int n_in,
                              void* d_out, int out_size) {
    const float* x  = (const float*)d_in[0];
    const float* W1 = (const float*)d_in[1];
    const float* b1 = (const float*)d_in[2];
    const float* W2 = (const float*)d_in[3];
    const float* b2 = (const float*)d_in[4];
    float* out = (float*)d_out;

    cudaFuncSetAttribute(snn_kernel,
                         cudaFuncAttributeMaxDynamicSharedMemorySize, DYN_SMEM);

    build_lut_kernel<<<(LUT_FLOATS + 255) / 256, 256>>>(W2);
    snn_kernel<<<BB / (4 * NB), 128, DYN_SMEM>>>(x, W1, b1, b2, out);
}